// round 2
// baseline (speedup 1.0000x reference)
#include <cuda_runtime.h>
#include <cuda_bf16.h>
#include <mma.h>
#include <math.h>

using namespace nvcuda;

#define B_   1024
#define G_   2000
#define GS_  25
#define H1_  1024
#define H2_  512
#define C_   10
#define EPS_ 1e-5f

// ---------------- scratch (device globals; no allocation allowed) ----------
__device__ float d_g [B_ * G_];     // 8 MB
__device__ float d_h1[B_ * H1_];    // 4 MB (raw, pre-BN)
__device__ float d_h2[B_ * H2_];    // 2 MB (raw, pre-BN)
__device__ float d_scale1[H1_], d_shift1[H1_];
__device__ float d_scale2[H2_], d_shift2[H2_];
__device__ float d_psum [8 * H1_];
__device__ float d_psum2[8 * H1_];

// ---------------- stage 1: grouped Linear(GS,1) + ReLU ---------------------
// g[b,j] = relu( sum_k x[b, j*25+k] * gene_w[j,k] + gene_b[j] )
#define GPB 256   // groups per block
__global__ __launch_bounds__(GPB)
void gene_kernel(const float* __restrict__ x,
                 const float* __restrict__ gw,
                 const float* __restrict__ gb,
                 float* __restrict__ g)
{
    __shared__ float sx[GPB * GS_];   // 25.6 KB
    const int b  = blockIdx.y;
    const int g0 = blockIdx.x * GPB;
    const int ng = min(GPB, G_ - g0);              // 256 or 208 — both *25 %4==0
    const float4* xrow = (const float4*)(x + (size_t)b * (G_ * GS_) + (size_t)g0 * GS_);
    const int nf4 = (ng * GS_) >> 2;
    float4* sx4 = (float4*)sx;
    for (int i = threadIdx.x; i < nf4; i += GPB)
        sx4[i] = xrow[i];
    __syncthreads();
    const int j = threadIdx.x;
    if (j < ng) {
        const float* w = gw + (size_t)(g0 + j) * GS_;
        float acc = __ldg(gb + g0 + j);
#pragma unroll
        for (int k = 0; k < GS_; k++)
            acc = fmaf(sx[j * GS_ + k], __ldg(w + k), acc);  // stride-25: conflict-free
        g[(size_t)b * G_ + g0 + j] = fmaxf(acc, 0.0f);
    }
}

// ---------------- TF32 tensor-core GEMM: C = A[MxK] * B[KxN] ---------------
// Block tile 128x64, BK=16, 256 threads = 8 warps (4 M x 2 N), warp tile 32x32.
// If BN_A: A is raw pre-BN activations; apply relu(a*scaleA[k]+shiftA[k]) on load.
#define TBM 128
#define TBN 64
#define TBK 16
template<bool BN_A>
__global__ __launch_bounds__(256)
void gemm_tf32(const float* __restrict__ A, const float* __restrict__ Bm,
               float* __restrict__ Cm,
               const float* __restrict__ scaleA, const float* __restrict__ shiftA,
               int M, int N, int K)
{
    __shared__ float As[TBM][TBK];   // 8 KB
    __shared__ float Bs[TBK][TBN];   // 4 KB

    const int tid  = threadIdx.x;
    const int warp = tid >> 5;
    const int wm   = warp >> 1;       // 0..3
    const int wn   = warp & 1;        // 0..1
    const int row0 = blockIdx.y * TBM;
    const int col0 = blockIdx.x * TBN;

    wmma::fragment<wmma::accumulator, 16, 16, 8, float> acc[2][2];
#pragma unroll
    for (int i = 0; i < 2; i++)
#pragma unroll
        for (int j = 0; j < 2; j++)
            wmma::fill_fragment(acc[i][j], 0.0f);

    for (int k0 = 0; k0 < K; k0 += TBK) {
        // --- A tile: 128x16 floats = 512 float4, 2 per thread ---
#pragma unroll
        for (int t = 0; t < 2; t++) {
            const int f  = tid + t * 256;
            const int r  = f >> 2;
            const int c4 = (f & 3) << 2;
            float4 v = *(const float4*)(A + (size_t)(row0 + r) * K + k0 + c4);
            if (BN_A) {
                const int kc = k0 + c4;
                v.x = fmaxf(fmaf(v.x, __ldg(scaleA + kc + 0), __ldg(shiftA + kc + 0)), 0.f);
                v.y = fmaxf(fmaf(v.y, __ldg(scaleA + kc + 1), __ldg(shiftA + kc + 1)), 0.f);
                v.z = fmaxf(fmaf(v.z, __ldg(scaleA + kc + 2), __ldg(shiftA + kc + 2)), 0.f);
                v.w = fmaxf(fmaf(v.w, __ldg(scaleA + kc + 3), __ldg(shiftA + kc + 3)), 0.f);
            }
            *(float4*)&As[r][c4] = v;
        }
        // --- B tile: 16x64 floats = 256 float4, 1 per thread ---
        {
            const int r  = tid >> 4;
            const int c4 = (tid & 15) << 2;
            *(float4*)&Bs[r][c4] =
                *(const float4*)(Bm + (size_t)(k0 + r) * N + col0 + c4);
        }
        __syncthreads();

#pragma unroll
        for (int ks = 0; ks < 2; ks++) {
            wmma::fragment<wmma::matrix_a, 16, 16, 8, wmma::precision::tf32, wmma::row_major> af[2];
            wmma::fragment<wmma::matrix_b, 16, 16, 8, wmma::precision::tf32, wmma::row_major> bf[2];
#pragma unroll
            for (int i = 0; i < 2; i++) {
                wmma::load_matrix_sync(af[i], &As[wm * 32 + i * 16][ks * 8], TBK);
#pragma unroll
                for (int t = 0; t < af[i].num_elements; t++)
                    af[i].x[t] = wmma::__float_to_tf32(af[i].x[t]);
            }
#pragma unroll
            for (int j = 0; j < 2; j++) {
                wmma::load_matrix_sync(bf[j], &Bs[ks * 8][wn * 32 + j * 16], TBN);
#pragma unroll
                for (int t = 0; t < bf[j].num_elements; t++)
                    bf[j].x[t] = wmma::__float_to_tf32(bf[j].x[t]);
            }
#pragma unroll
            for (int i = 0; i < 2; i++)
#pragma unroll
                for (int j = 0; j < 2; j++)
                    wmma::mma_sync(acc[i][j], af[i], bf[j], acc[i][j]);
        }
        __syncthreads();
    }

#pragma unroll
    for (int i = 0; i < 2; i++)
#pragma unroll
        for (int j = 0; j < 2; j++)
            wmma::store_matrix_sync(
                Cm + (size_t)(row0 + wm * 32 + i * 16) * N + col0 + wn * 32 + j * 16,
                acc[i][j], N, wmma::mem_row_major);
}

// ---------------- BN stats: two-stage partial sums -------------------------
// stage 1: grid (N/64, 8), block (16, 32). Each block: 64 cols x 128 rows.
__global__ __launch_bounds__(512)
void bn_part(const float* __restrict__ h, float* __restrict__ psum,
             float* __restrict__ psum2, int N)
{
    const int tx = threadIdx.x, ty = threadIdx.y;
    const int cb = blockIdx.x * 64 + tx * 4;
    const int r0 = blockIdx.y * 128 + ty;
    float4 s  = {0.f, 0.f, 0.f, 0.f};
    float4 s2 = {0.f, 0.f, 0.f, 0.f};
#pragma unroll
    for (int i = 0; i < 4; i++) {
        const float4 v = *(const float4*)(h + (size_t)(r0 + i * 32) * N + cb);
        s.x += v.x; s.y += v.y; s.z += v.z; s.w += v.w;
        s2.x += v.x * v.x; s2.y += v.y * v.y; s2.z += v.z * v.z; s2.w += v.w * v.w;
    }
    __shared__ float4 sh [32][16];
    __shared__ float4 sh2[32][16];
    sh[ty][tx] = s; sh2[ty][tx] = s2;
    __syncthreads();
    for (int off = 16; off > 0; off >>= 1) {
        if (ty < off) {
            float4 a = sh[ty + off][tx], b = sh2[ty + off][tx];
            float4 c = sh[ty][tx],       d = sh2[ty][tx];
            c.x += a.x; c.y += a.y; c.z += a.z; c.w += a.w;
            d.x += b.x; d.y += b.y; d.z += b.z; d.w += b.w;
            sh[ty][tx] = c; sh2[ty][tx] = d;
        }
        __syncthreads();
    }
    if (ty == 0) {
        *(float4*)(psum  + (size_t)blockIdx.y * N + cb) = sh [0][tx];
        *(float4*)(psum2 + (size_t)blockIdx.y * N + cb) = sh2[0][tx];
    }
}

// stage 2: finalize scale/shift (bias folded: mean_eff = s/B + bias)
__global__ void bn_final(const float* __restrict__ psum, const float* __restrict__ psum2,
                         const float* __restrict__ bias,
                         const float* __restrict__ gamma, const float* __restrict__ beta,
                         float* __restrict__ scale, float* __restrict__ shift, int N)
{
    const int c = blockIdx.x * 256 + threadIdx.x;
    if (c >= N) return;
    float s = 0.f, s2 = 0.f;
#pragma unroll
    for (int i = 0; i < 8; i++) { s += psum[i * N + c]; s2 += psum2[i * N + c]; }
    const float inv = 1.0f / (float)B_;
    const float mu  = s * inv;
    const float var = fmaxf(s2 * inv - mu * mu, 0.0f);
    const float sc  = __ldg(gamma + c) * rsqrtf(var + EPS_);
    scale[c] = sc;
    shift[c] = __ldg(beta + c) - (mu + __ldg(bias + c)) * sc;
}

// ---------------- final: bn2(h2raw)@Wout + g@Wres + biases -> softmax ------
__global__ __launch_bounds__(256)
void final_kernel(const float* __restrict__ g, const float* __restrict__ h2raw,
                  const float* __restrict__ scale2, const float* __restrict__ shift2,
                  const float* __restrict__ Wout, const float* __restrict__ bout,
                  const float* __restrict__ Wres, const float* __restrict__ bres,
                  float* __restrict__ out)
{
    const int b = blockIdx.x;
    float acc[C_] = {};

    for (int k = threadIdx.x; k < H2_; k += 256) {
        const float hv = fmaxf(fmaf(h2raw[(size_t)b * H2_ + k],
                                    __ldg(scale2 + k), __ldg(shift2 + k)), 0.0f);
        const float* w = Wout + (size_t)k * C_;
#pragma unroll
        for (int c = 0; c < C_; c++) acc[c] = fmaf(hv, __ldg(w + c), acc[c]);
    }
    for (int j = threadIdx.x; j < G_; j += 256) {
        const float gv = g[(size_t)b * G_ + j];
        const float* w = Wres + (size_t)j * C_;
#pragma unroll
        for (int c = 0; c < C_; c++) acc[c] = fmaf(gv, __ldg(w + c), acc[c]);
    }

#pragma unroll
    for (int c = 0; c < C_; c++)
#pragma unroll
        for (int off = 16; off > 0; off >>= 1)
            acc[c] += __shfl_down_sync(0xFFFFFFFFu, acc[c], off);

    __shared__ float red[8][C_];
    const int warp = threadIdx.x >> 5;
    const int lane = threadIdx.x & 31;
    if (lane == 0)
#pragma unroll
        for (int c = 0; c < C_; c++) red[warp][c] = acc[c];
    __syncthreads();

    if (threadIdx.x == 0) {
        float logits[C_];
#pragma unroll
        for (int c = 0; c < C_; c++) {
            float v = __ldg(bout + c) + __ldg(bres + c);
#pragma unroll
            for (int w = 0; w < 8; w++) v += red[w][c];
            logits[c] = v;
        }
        float m = logits[0];
#pragma unroll
        for (int c = 1; c < C_; c++) m = fmaxf(m, logits[c]);
        float sum = 0.f;
#pragma unroll
        for (int c = 0; c < C_; c++) { logits[c] = __expf(logits[c] - m); sum += logits[c]; }
        const float inv = 1.0f / sum;
#pragma unroll
        for (int c = 0; c < C_; c++) out[(size_t)b * C_ + c] = logits[c] * inv;
    }
}

// ---------------- launch ----------------------------------------------------
extern "C" void kernel_launch(void* const* d_in, const int* in_sizes, int n_in,
                              void* d_out, int out_size)
{
    const float* x      = (const float*)d_in[0];
    const float* gene_w = (const float*)d_in[1];
    const float* gene_b = (const float*)d_in[2];
    const float* W1     = (const float*)d_in[3];
    const float* b1     = (const float*)d_in[4];
    const float* gamma1 = (const float*)d_in[5];
    const float* beta1  = (const float*)d_in[6];
    const float* W2     = (const float*)d_in[7];
    const float* b2     = (const float*)d_in[8];
    const float* gamma2 = (const float*)d_in[9];
    const float* beta2  = (const float*)d_in[10];
    const float* Wout   = (const float*)d_in[11];
    const float* bout   = (const float*)d_in[12];
    const float* Wres   = (const float*)d_in[13];
    const float* bres   = (const float*)d_in[14];
    float* out = (float*)d_out;

    float *g_p, *h1_p, *h2_p, *sc1_p, *sh1_p, *sc2_p, *sh2_p, *ps_p, *ps2_p;
    cudaGetSymbolAddress((void**)&g_p,   d_g);
    cudaGetSymbolAddress((void**)&h1_p,  d_h1);
    cudaGetSymbolAddress((void**)&h2_p,  d_h2);
    cudaGetSymbolAddress((void**)&sc1_p, d_scale1);
    cudaGetSymbolAddress((void**)&sh1_p, d_shift1);
    cudaGetSymbolAddress((void**)&sc2_p, d_scale2);
    cudaGetSymbolAddress((void**)&sh2_p, d_shift2);
    cudaGetSymbolAddress((void**)&ps_p,  d_psum);
    cudaGetSymbolAddress((void**)&ps2_p, d_psum2);

    // 1) grouped gene layer -> g
    gene_kernel<<<dim3((G_ + GPB - 1) / GPB, B_), GPB>>>(x, gene_w, gene_b, g_p);

    // 2) h1raw = g @ W1   (TF32 tensor cores; bias folded into BN)
    gemm_tf32<false><<<dim3(H1_ / TBN, B_ / TBM), 256>>>(
        g_p, W1, h1_p, nullptr, nullptr, B_, H1_, G_);

    // 3) BN1 -> scale1/shift1
    bn_part<<<dim3(H1_ / 64, 8), dim3(16, 32)>>>(h1_p, ps_p, ps2_p, H1_);
    bn_final<<<(H1_ + 255) / 256, 256>>>(ps_p, ps2_p, b1, gamma1, beta1, sc1_p, sh1_p, H1_);

    // 4) h2raw = relu(bn1(h1raw)) @ W2  (BN applied during A load)
    gemm_tf32<true><<<dim3(H2_ / TBN, B_ / TBM), 256>>>(
        h1_p, W2, h2_p, sc1_p, sh1_p, B_, H2_, H1_);

    // 5) BN2 -> scale2/shift2
    bn_part<<<dim3(H2_ / 64, 8), dim3(16, 32)>>>(h2_p, ps_p, ps2_p, H2_);
    bn_final<<<(H2_ + 255) / 256, 256>>>(ps_p, ps2_p, b2, gamma2, beta2, sc2_p, sh2_p, H2_);

    // 6) fused output heads + softmax (BN2 applied on the fly)
    final_kernel<<<B_, 256>>>(g_p, h2_p, sc2_p, sh2_p, Wout, bout, Wres, bres, out);
}

// round 4
// speedup vs baseline: 1.1430x; 1.1430x over previous
#include <cuda_runtime.h>
#include <cuda_bf16.h>
#include <mma.h>
#include <math.h>
#include <stdint.h>

using namespace nvcuda;

#define B_   1024
#define G_   2000
#define GS_  25
#define KP_  2048      // padded K for gemm1
#define H1_  1024
#define H2_  512
#define C_   10
#define EPS_ 1e-5f

// ---------------- scratch (device globals; no allocation allowed) ----------
__device__ float d_g  [B_ * KP_];     // 8 MB  (tf32-rounded, zero-padded)
__device__ float d_W1p[KP_ * H1_];    // 8 MB  (W1 padded K->2048, tf32-rounded)
__device__ float d_W2r[H1_ * H2_];    // 2 MB  (W2 tf32-rounded)
__device__ float d_h1 [B_ * H1_];     // 4 MB  (raw, pre-BN)
__device__ float d_h1a[B_ * H1_];     // 4 MB  (relu(bn1(h1)), tf32-rounded)
__device__ float d_h2 [B_ * H2_];     // 2 MB  (raw, pre-BN)
__device__ float d_scale1[H1_], d_shift1[H1_];
__device__ float d_scale2[H2_], d_shift2[H2_];
__device__ float d_psum [8 * H1_];
__device__ float d_psum2[8 * H1_];

// ---------------- helpers ---------------------------------------------------
__device__ __forceinline__ float to_tf32(float x) {
    float r; asm("cvt.rna.tf32.f32 %0, %1;" : "=f"(r) : "f"(x)); return r;
}
__device__ __forceinline__ uint32_t smem_u32(const void* p) {
    return (uint32_t)__cvta_generic_to_shared(p);
}
#define CP_ASYNC16(dst_u32, src) \
    asm volatile("cp.async.cg.shared.global [%0], [%1], 16;" :: "r"(dst_u32), "l"(src))
#define CP_COMMIT() asm volatile("cp.async.commit_group;")
#define CP_WAIT(n)  asm volatile("cp.async.wait_group %0;" :: "n"(n))

// ---------------- weight prep: tf32 round (+ K pad for W1) -----------------
__global__ void prep_w1(const float* __restrict__ W1, float* __restrict__ W1p)
{
    const int idx = blockIdx.x * 256 + threadIdx.x;   // over KP_*H1_
    const int k = idx >> 10;                          // H1_=1024
    W1p[idx] = (k < G_) ? to_tf32(W1[(size_t)k * H1_ + (idx & 1023)]) : 0.0f;
}
__global__ void prep_w2(const float* __restrict__ W2, float* __restrict__ W2r)
{
    const int idx = blockIdx.x * 256 + threadIdx.x;   // over H1_*H2_
    W2r[idx] = to_tf32(W2[idx]);
}

// ---------------- stage 1: grouped Linear(GS,1) + ReLU -> tf32 g -----------
#define GPB 256
__global__ __launch_bounds__(GPB)
void gene_kernel(const float* __restrict__ x,
                 const float* __restrict__ gw,
                 const float* __restrict__ gb,
                 float* __restrict__ g)
{
    __shared__ float sx[GPB * GS_];
    const int b  = blockIdx.y;
    const int g0 = blockIdx.x * GPB;
    const int ng = min(GPB, G_ - g0);
    const float4* xrow = (const float4*)(x + (size_t)b * (G_ * GS_) + (size_t)g0 * GS_);
    const int nf4 = (ng * GS_) >> 2;
    float4* sx4 = (float4*)sx;
    for (int i = threadIdx.x; i < nf4; i += GPB) sx4[i] = xrow[i];
    __syncthreads();
    const int j = threadIdx.x;
    if (j < ng) {
        const float* w = gw + (size_t)(g0 + j) * GS_;
        float acc = __ldg(gb + g0 + j);
#pragma unroll
        for (int k = 0; k < GS_; k++)
            acc = fmaf(sx[j * GS_ + k], __ldg(w + k), acc);
        g[(size_t)b * KP_ + g0 + j] = to_tf32(fmaxf(acc, 0.0f));
    } else {
        const int col = g0 + j;
        if (col < KP_) g[(size_t)b * KP_ + col] = 0.0f;   // zero K-pad
    }
}

// ---------------- TF32 wmma GEMM: C[M,N] = A[M,K] @ B[K,N] -----------------
// CTA tile 64x64, BK=32, 128 threads = 4 warps (2x2), warp tile 32x32.
// cp.async double-buffered. A,B pre-rounded to tf32 in memory.
#define WBM 64
#define WBN 64
#define WBK 32
#define LDA 40   // 32 + 8 pad
#define LDB 72   // 64 + 8 pad
__global__ __launch_bounds__(128, 2)
void wgemm(const float* __restrict__ A, const float* __restrict__ Bm,
           float* __restrict__ Cm, int M, int N, int K)
{
    __shared__ __align__(16) float As[2][WBM][LDA];
    __shared__ __align__(16) float Bs[2][WBK][LDB];

    const int tid  = threadIdx.x;
    const int warp = tid >> 5;
    const int wm   = warp >> 1;
    const int wn   = warp & 1;
    const int row0 = blockIdx.y * WBM;
    const int col0 = blockIdx.x * WBN;
    const int nc   = K >> 5;

    wmma::fragment<wmma::accumulator, 16, 16, 8, float> acc[2][2];
#pragma unroll
    for (int i = 0; i < 2; i++)
#pragma unroll
        for (int j = 0; j < 2; j++)
            wmma::fill_fragment(acc[i][j], 0.0f);

    // per-thread cp.async slots
    // A: 64x32 floats = 512 f4 -> 4/thread. thread t, i: idx=t+i*128; r=idx>>3; c=(idx&7)*4
    // B: 32x64 floats = 512 f4 -> 4/thread.              idx=t+i*128; r=idx>>4; c=(idx&15)*4
    auto load_tiles = [&](int bsel, int c) {
        const int k0 = c << 5;
#pragma unroll
        for (int i = 0; i < 4; i++) {
            const int idx = tid + i * 128;
            const int r = idx >> 3, cc = (idx & 7) << 2;
            CP_ASYNC16(smem_u32(&As[bsel][r][cc]),
                       A + (size_t)(row0 + r) * K + k0 + cc);
        }
#pragma unroll
        for (int i = 0; i < 4; i++) {
            const int idx = tid + i * 128;
            const int r = idx >> 4, cc = (idx & 15) << 2;
            CP_ASYNC16(smem_u32(&Bs[bsel][r][cc]),
                       Bm + (size_t)(k0 + r) * N + col0 + cc);
        }
    };

    load_tiles(0, 0);
    CP_COMMIT();

    for (int c = 0; c < nc; c++) {
        const int bsel = c & 1;
        if (c + 1 < nc) {
            load_tiles(bsel ^ 1, c + 1);
            CP_COMMIT();
            CP_WAIT(1);
        } else {
            CP_WAIT(0);
        }
        __syncthreads();

#pragma unroll
        for (int ks = 0; ks < 4; ks++) {
            wmma::fragment<wmma::matrix_a, 16, 16, 8, wmma::precision::tf32, wmma::row_major> af[2];
            wmma::fragment<wmma::matrix_b, 16, 16, 8, wmma::precision::tf32, wmma::row_major> bf[2];
            wmma::load_matrix_sync(af[0], &As[bsel][wm * 32     ][ks * 8], LDA);
            wmma::load_matrix_sync(af[1], &As[bsel][wm * 32 + 16][ks * 8], LDA);
            wmma::load_matrix_sync(bf[0], &Bs[bsel][ks * 8][wn * 32     ], LDB);
            wmma::load_matrix_sync(bf[1], &Bs[bsel][ks * 8][wn * 32 + 16], LDB);
#pragma unroll
            for (int i = 0; i < 2; i++)
#pragma unroll
                for (int j = 0; j < 2; j++)
                    wmma::mma_sync(acc[i][j], af[i], bf[j], acc[i][j]);
        }
        __syncthreads();
    }

#pragma unroll
    for (int i = 0; i < 2; i++)
#pragma unroll
        for (int j = 0; j < 2; j++)
            wmma::store_matrix_sync(
                Cm + (size_t)(row0 + wm * 32 + i * 16) * N + col0 + wn * 32 + j * 16,
                acc[i][j], N, wmma::mem_row_major);
}

// ---------------- BN stats: two-stage partial sums -------------------------
__global__ __launch_bounds__(512)
void bn_part(const float* __restrict__ h, float* __restrict__ psum,
             float* __restrict__ psum2, int N)
{
    const int tx = threadIdx.x, ty = threadIdx.y;
    const int cb = blockIdx.x * 64 + tx * 4;
    const int r0 = blockIdx.y * 128 + ty;
    float4 s  = {0.f, 0.f, 0.f, 0.f};
    float4 s2 = {0.f, 0.f, 0.f, 0.f};
#pragma unroll
    for (int i = 0; i < 4; i++) {
        const float4 v = *(const float4*)(h + (size_t)(r0 + i * 32) * N + cb);
        s.x += v.x; s.y += v.y; s.z += v.z; s.w += v.w;
        s2.x += v.x * v.x; s2.y += v.y * v.y; s2.z += v.z * v.z; s2.w += v.w * v.w;
    }
    __shared__ float4 sh [32][16];
    __shared__ float4 sh2[32][16];
    sh[ty][tx] = s; sh2[ty][tx] = s2;
    __syncthreads();
    for (int off = 16; off > 0; off >>= 1) {
        if (ty < off) {
            float4 a = sh[ty + off][tx], b = sh2[ty + off][tx];
            float4 c = sh[ty][tx],       d = sh2[ty][tx];
            c.x += a.x; c.y += a.y; c.z += a.z; c.w += a.w;
            d.x += b.x; d.y += b.y; d.z += b.z; d.w += b.w;
            sh[ty][tx] = c; sh2[ty][tx] = d;
        }
        __syncthreads();
    }
    if (ty == 0) {
        *(float4*)(psum  + (size_t)blockIdx.y * N + cb) = sh [0][tx];
        *(float4*)(psum2 + (size_t)blockIdx.y * N + cb) = sh2[0][tx];
    }
}

__global__ void bn_final(const float* __restrict__ psum, const float* __restrict__ psum2,
                         const float* __restrict__ bias,
                         const float* __restrict__ gamma, const float* __restrict__ beta,
                         float* __restrict__ scale, float* __restrict__ shift, int N)
{
    const int c = blockIdx.x * 256 + threadIdx.x;
    if (c >= N) return;
    float s = 0.f, s2 = 0.f;
#pragma unroll
    for (int i = 0; i < 8; i++) { s += psum[i * N + c]; s2 += psum2[i * N + c]; }
    const float inv = 1.0f / (float)B_;
    const float mu  = s * inv;
    const float var = fmaxf(s2 * inv - mu * mu, 0.0f);
    const float sc  = __ldg(gamma + c) * rsqrtf(var + EPS_);
    scale[c] = sc;
    shift[c] = __ldg(beta + c) - (mu + __ldg(bias + c)) * sc;
}

// ---------------- BN apply + ReLU + tf32 round -----------------------------
__global__ void bn_apply_round(const float* __restrict__ hin, float* __restrict__ hout,
                               const float* __restrict__ scale,
                               const float* __restrict__ shift, int N)
{
    const int col = blockIdx.x * 256 + threadIdx.x;
    const size_t idx = (size_t)blockIdx.y * N + col;
    hout[idx] = to_tf32(fmaxf(fmaf(hin[idx], __ldg(scale + col), __ldg(shift + col)), 0.0f));
}

// ---------------- final: bn2(h2raw)@Wout + g@Wres + biases -> softmax ------
__global__ __launch_bounds__(256)
void final_kernel(const float* __restrict__ g, const float* __restrict__ h2raw,
                  const float* __restrict__ scale2, const float* __restrict__ shift2,
                  const float* __restrict__ Wout, const float* __restrict__ bout,
                  const float* __restrict__ Wres, const float* __restrict__ bres,
                  float* __restrict__ out)
{
    const int b = blockIdx.x;
    float acc[C_] = {};

    for (int k = threadIdx.x; k < H2_; k += 256) {
        const float hv = fmaxf(fmaf(h2raw[(size_t)b * H2_ + k],
                                    __ldg(scale2 + k), __ldg(shift2 + k)), 0.0f);
        const float* w = Wout + (size_t)k * C_;
#pragma unroll
        for (int c = 0; c < C_; c++) acc[c] = fmaf(hv, __ldg(w + c), acc[c]);
    }
    for (int j = threadIdx.x; j < G_; j += 256) {
        const float gv = g[(size_t)b * KP_ + j];
        const float* w = Wres + (size_t)j * C_;
#pragma unroll
        for (int c = 0; c < C_; c++) acc[c] = fmaf(gv, __ldg(w + c), acc[c]);
    }

#pragma unroll
    for (int c = 0; c < C_; c++)
#pragma unroll
        for (int off = 16; off > 0; off >>= 1)
            acc[c] += __shfl_down_sync(0xFFFFFFFFu, acc[c], off);

    __shared__ float red[8][C_];
    const int warp = threadIdx.x >> 5;
    const int lane = threadIdx.x & 31;
    if (lane == 0)
#pragma unroll
        for (int c = 0; c < C_; c++) red[warp][c] = acc[c];
    __syncthreads();

    if (threadIdx.x == 0) {
        float logits[C_];
#pragma unroll
        for (int c = 0; c < C_; c++) {
            float v = __ldg(bout + c) + __ldg(bres + c);
#pragma unroll
            for (int w = 0; w < 8; w++) v += red[w][c];
            logits[c] = v;
        }
        float m = logits[0];
#pragma unroll
        for (int c = 1; c < C_; c++) m = fmaxf(m, logits[c]);
        float sum = 0.f;
#pragma unroll
        for (int c = 0; c < C_; c++) { logits[c] = __expf(logits[c] - m); sum += logits[c]; }
        const float inv = 1.0f / sum;
#pragma unroll
        for (int c = 0; c < C_; c++) out[(size_t)b * C_ + c] = logits[c] * inv;
    }
}

// ---------------- launch ----------------------------------------------------
extern "C" void kernel_launch(void* const* d_in, const int* in_sizes, int n_in,
                              void* d_out, int out_size)
{
    const float* x      = (const float*)d_in[0];
    const float* gene_w = (const float*)d_in[1];
    const float* gene_b = (const float*)d_in[2];
    const float* W1     = (const float*)d_in[3];
    const float* b1     = (const float*)d_in[4];
    const float* gamma1 = (const float*)d_in[5];
    const float* beta1  = (const float*)d_in[6];
    const float* W2     = (const float*)d_in[7];
    const float* b2     = (const float*)d_in[8];
    const float* gamma2 = (const float*)d_in[9];
    const float* beta2  = (const float*)d_in[10];
    const float* Wout   = (const float*)d_in[11];
    const float* bout   = (const float*)d_in[12];
    const float* Wres   = (const float*)d_in[13];
    const float* bres   = (const float*)d_in[14];
    float* out = (float*)d_out;

    float *g_p, *w1_p, *w2_p, *h1_p, *h1a_p, *h2_p;
    float *sc1_p, *sh1_p, *sc2_p, *sh2_p, *ps_p, *ps2_p;
    cudaGetSymbolAddress((void**)&g_p,   d_g);
    cudaGetSymbolAddress((void**)&w1_p,  d_W1p);
    cudaGetSymbolAddress((void**)&w2_p,  d_W2r);
    cudaGetSymbolAddress((void**)&h1_p,  d_h1);
    cudaGetSymbolAddress((void**)&h1a_p, d_h1a);
    cudaGetSymbolAddress((void**)&h2_p,  d_h2);
    cudaGetSymbolAddress((void**)&sc1_p, d_scale1);
    cudaGetSymbolAddress((void**)&sh1_p, d_shift1);
    cudaGetSymbolAddress((void**)&sc2_p, d_scale2);
    cudaGetSymbolAddress((void**)&sh2_p, d_shift2);
    cudaGetSymbolAddress((void**)&ps_p,  d_psum);
    cudaGetSymbolAddress((void**)&ps2_p, d_psum2);

    // 0) weight prep (round + pad)
    prep_w1<<<(KP_ * H1_) / 256, 256>>>(W1, w1_p);
    prep_w2<<<(H1_ * H2_) / 256, 256>>>(W2, w2_p);

    // 1) grouped gene layer -> g (tf32, K-padded)
    gene_kernel<<<dim3((G_ + GPB - 1) / GPB, B_), GPB>>>(x, gene_w, gene_b, g_p);

    // 2) h1raw = g @ W1p  (wmma tf32, cp.async double-buffered)
    wgemm<<<dim3(H1_ / WBN, B_ / WBM), 128>>>(g_p, w1_p, h1_p, B_, H1_, KP_);

    // 3) BN1 -> scale1/shift1 (b1 folded); apply+round -> h1a
    bn_part<<<dim3(H1_ / 64, 8), dim3(16, 32)>>>(h1_p, ps_p, ps2_p, H1_);
    bn_final<<<(H1_ + 255) / 256, 256>>>(ps_p, ps2_p, b1, gamma1, beta1, sc1_p, sh1_p, H1_);
    bn_apply_round<<<dim3(H1_ / 256, B_), 256>>>(h1_p, h1a_p, sc1_p, sh1_p, H1_);

    // 4) h2raw = h1a @ W2r
    wgemm<<<dim3(H2_ / WBN, B_ / WBM), 128>>>(h1a_p, w2_p, h2_p, B_, H2_, H1_);

    // 5) BN2 -> scale2/shift2
    bn_part<<<dim3(H2_ / 64, 8), dim3(16, 32)>>>(h2_p, ps_p, ps2_p, H2_);
    bn_final<<<(H2_ + 255) / 256, 256>>>(ps_p, ps2_p, b2, gamma2, beta2, sc2_p, sh2_p, H2_);

    // 6) fused output heads + softmax
    final_kernel<<<B_, 256>>>(g_p, h2_p, sc2_p, sh2_p, Wout, bout, Wres, bres, out);
}

// round 5
// speedup vs baseline: 1.5837x; 1.3855x over previous
#include <cuda_runtime.h>
#include <cuda_bf16.h>
#include <mma.h>
#include <math.h>
#include <stdint.h>

using namespace nvcuda;

#define B_   1024
#define G_   2000
#define GS_  25
#define KP_  2048      // padded K for gemm1
#define H1_  1024
#define H2_  512
#define C_   10
#define EPS_ 1e-5f

// ---------------- scratch (device globals; no allocation allowed) ----------
__device__ float d_g  [B_ * KP_];     // 8 MB  (tf32-rounded, zero-padded)
__device__ float d_W1p[KP_ * H1_];    // 8 MB  (W1 padded K->2048, tf32-rounded)
__device__ float d_W2r[H1_ * H2_];    // 2 MB  (W2 tf32-rounded)
__device__ float d_h1 [B_ * H1_];     // 4 MB  (raw, pre-BN)
__device__ float d_h1a[B_ * H1_];     // 4 MB  (relu(bn1(h1)), tf32-rounded)
__device__ float d_h2 [B_ * H2_];     // 2 MB  (raw, pre-BN)
__device__ float d_scale1[H1_], d_shift1[H1_];
__device__ float d_scale2[H2_], d_shift2[H2_];
__device__ float d_psum [8 * H1_];
__device__ float d_psum2[8 * H1_];

// ---------------- helpers ---------------------------------------------------
__device__ __forceinline__ float to_tf32(float x) {
    float r; asm("cvt.rna.tf32.f32 %0, %1;" : "=f"(r) : "f"(x)); return r;
}
__device__ __forceinline__ uint32_t smem_u32(const void* p) {
    return (uint32_t)__cvta_generic_to_shared(p);
}
#define CP_ASYNC16(dst_u32, src) \
    asm volatile("cp.async.cg.shared.global [%0], [%1], 16;" :: "r"(dst_u32), "l"(src))
#define CP_COMMIT() asm volatile("cp.async.commit_group;")
#define CP_WAIT(n)  asm volatile("cp.async.wait_group %0;" :: "n"(n))

// ---------------- weight prep: tf32 round (+ K pad for W1) -----------------
__global__ void prep_w1(const float* __restrict__ W1, float* __restrict__ W1p)
{
    const int idx = blockIdx.x * 256 + threadIdx.x;   // over KP_*H1_
    const int k = idx >> 10;                          // H1_=1024
    W1p[idx] = (k < G_) ? to_tf32(W1[(size_t)k * H1_ + (idx & 1023)]) : 0.0f;
}
__global__ void prep_w2(const float* __restrict__ W2, float* __restrict__ W2r)
{
    const int idx = blockIdx.x * 256 + threadIdx.x;   // over H1_*H2_
    W2r[idx] = to_tf32(W2[idx]);
}

// ---------------- stage 1: grouped Linear(GS,1) + ReLU -> tf32 g -----------
#define GPB 256
__global__ __launch_bounds__(GPB)
void gene_kernel(const float* __restrict__ x,
                 const float* __restrict__ gw,
                 const float* __restrict__ gb,
                 float* __restrict__ g)
{
    __shared__ float sx[GPB * GS_];
    const int b  = blockIdx.y;
    const int g0 = blockIdx.x * GPB;
    const int ng = min(GPB, G_ - g0);
    const float4* xrow = (const float4*)(x + (size_t)b * (G_ * GS_) + (size_t)g0 * GS_);
    const int nf4 = (ng * GS_) >> 2;
    float4* sx4 = (float4*)sx;
    for (int i = threadIdx.x; i < nf4; i += GPB) sx4[i] = xrow[i];
    __syncthreads();
    const int j = threadIdx.x;
    if (j < ng) {
        const float* w = gw + (size_t)(g0 + j) * GS_;
        float acc = __ldg(gb + g0 + j);
#pragma unroll
        for (int k = 0; k < GS_; k++)
            acc = fmaf(sx[j * GS_ + k], __ldg(w + k), acc);
        g[(size_t)b * KP_ + g0 + j] = to_tf32(fmaxf(acc, 0.0f));
    } else {
        const int col = g0 + j;
        if (col < KP_) g[(size_t)b * KP_ + col] = 0.0f;   // zero K-pad
    }
}

// ---------------- TF32 wmma GEMM: C[M,N] = A[M,K] @ B[K,N] -----------------
// CTA tile 64x64, BK=32, 128 threads = 4 warps (2x2), warp tile 32x32.
// cp.async double-buffered; 4 CTAs/SM (occupancy was the R4 bottleneck).
#define WBM 64
#define WBN 64
#define WBK 32
#define LDA 40   // 32 + 8 pad
#define LDB 72   // 64 + 8 pad
__global__ __launch_bounds__(128, 4)
void wgemm(const float* __restrict__ A, const float* __restrict__ Bm,
           float* __restrict__ Cm, int M, int N, int K)
{
    __shared__ __align__(16) float As[2][WBM][LDA];
    __shared__ __align__(16) float Bs[2][WBK][LDB];

    const int tid  = threadIdx.x;
    const int warp = tid >> 5;
    const int wm   = warp >> 1;
    const int wn   = warp & 1;
    const int row0 = blockIdx.y * WBM;
    const int col0 = blockIdx.x * WBN;
    const int nc   = K >> 5;

    // hoisted per-thread addresses (reduce live regs in the loop)
    const int ar0 = tid >> 3, ac0 = (tid & 7) << 2;         // A: 64 rows x 8 f4
    const int br0 = tid >> 4, bc0 = (tid & 15) << 2;        // B: 32 rows x 16 f4
    const float* ag0 = A  + (size_t)(row0 + ar0) * K + ac0;       // + i*16 rows
    const float* bg0 = Bm + (size_t)br0 * N + col0 + bc0;         // + i*8 rows, + k0*N
    const size_t aStep = (size_t)16 * K;
    const size_t bStep = (size_t)8 * N;

    uint32_t aDst[2][4], bDst[2][4];
#pragma unroll
    for (int s = 0; s < 2; s++)
#pragma unroll
        for (int i = 0; i < 4; i++) {
            aDst[s][i] = smem_u32(&As[s][ar0 + i * 16][ac0]);
            bDst[s][i] = smem_u32(&Bs[s][br0 + i * 8][bc0]);
        }

    wmma::fragment<wmma::accumulator, 16, 16, 8, float> acc[2][2];
#pragma unroll
    for (int i = 0; i < 2; i++)
#pragma unroll
        for (int j = 0; j < 2; j++)
            wmma::fill_fragment(acc[i][j], 0.0f);

    // prefetch chunk 0
#pragma unroll
    for (int i = 0; i < 4; i++) CP_ASYNC16(aDst[0][i], ag0 + i * aStep);
#pragma unroll
    for (int i = 0; i < 4; i++) CP_ASYNC16(bDst[0][i], bg0 + i * bStep);
    CP_COMMIT();

    for (int c = 0; c < nc; c++) {
        const int bsel = c & 1;
        if (c + 1 < nc) {
            const int k0 = (c + 1) << 5;
            const float* ap = ag0 + k0;
            const float* bp = bg0 + (size_t)k0 * N;
#pragma unroll
            for (int i = 0; i < 4; i++) CP_ASYNC16(aDst[bsel ^ 1][i], ap + i * aStep);
#pragma unroll
            for (int i = 0; i < 4; i++) CP_ASYNC16(bDst[bsel ^ 1][i], bp + i * bStep);
            CP_COMMIT();
            CP_WAIT(1);
        } else {
            CP_WAIT(0);
        }
        __syncthreads();

#pragma unroll
        for (int ks = 0; ks < 4; ks++) {
            wmma::fragment<wmma::matrix_a, 16, 16, 8, wmma::precision::tf32, wmma::row_major> af[2];
            wmma::fragment<wmma::matrix_b, 16, 16, 8, wmma::precision::tf32, wmma::row_major> bf[2];
            wmma::load_matrix_sync(af[0], &As[bsel][wm * 32     ][ks * 8], LDA);
            wmma::load_matrix_sync(af[1], &As[bsel][wm * 32 + 16][ks * 8], LDA);
            wmma::load_matrix_sync(bf[0], &Bs[bsel][ks * 8][wn * 32     ], LDB);
            wmma::load_matrix_sync(bf[1], &Bs[bsel][ks * 8][wn * 32 + 16], LDB);
#pragma unroll
            for (int i = 0; i < 2; i++)
#pragma unroll
                for (int j = 0; j < 2; j++)
                    wmma::mma_sync(acc[i][j], af[i], bf[j], acc[i][j]);
        }
        __syncthreads();
    }

#pragma unroll
    for (int i = 0; i < 2; i++)
#pragma unroll
        for (int j = 0; j < 2; j++)
            wmma::store_matrix_sync(
                Cm + (size_t)(row0 + wm * 32 + i * 16) * N + col0 + wn * 32 + j * 16,
                acc[i][j], N, wmma::mem_row_major);
}

// ---------------- BN stats: two-stage partial sums -------------------------
__global__ __launch_bounds__(512)
void bn_part(const float* __restrict__ h, float* __restrict__ psum,
             float* __restrict__ psum2, int N)
{
    const int tx = threadIdx.x, ty = threadIdx.y;
    const int cb = blockIdx.x * 64 + tx * 4;
    const int r0 = blockIdx.y * 128 + ty;
    float4 s  = {0.f, 0.f, 0.f, 0.f};
    float4 s2 = {0.f, 0.f, 0.f, 0.f};
#pragma unroll
    for (int i = 0; i < 4; i++) {
        const float4 v = *(const float4*)(h + (size_t)(r0 + i * 32) * N + cb);
        s.x += v.x; s.y += v.y; s.z += v.z; s.w += v.w;
        s2.x += v.x * v.x; s2.y += v.y * v.y; s2.z += v.z * v.z; s2.w += v.w * v.w;
    }
    __shared__ float4 sh [32][16];
    __shared__ float4 sh2[32][16];
    sh[ty][tx] = s; sh2[ty][tx] = s2;
    __syncthreads();
    for (int off = 16; off > 0; off >>= 1) {
        if (ty < off) {
            float4 a = sh[ty + off][tx], b = sh2[ty + off][tx];
            float4 c = sh[ty][tx],       d = sh2[ty][tx];
            c.x += a.x; c.y += a.y; c.z += a.z; c.w += a.w;
            d.x += b.x; d.y += b.y; d.z += b.z; d.w += b.w;
            sh[ty][tx] = c; sh2[ty][tx] = d;
        }
        __syncthreads();
    }
    if (ty == 0) {
        *(float4*)(psum  + (size_t)blockIdx.y * N + cb) = sh [0][tx];
        *(float4*)(psum2 + (size_t)blockIdx.y * N + cb) = sh2[0][tx];
    }
}

__global__ void bn_final(const float* __restrict__ psum, const float* __restrict__ psum2,
                         const float* __restrict__ bias,
                         const float* __restrict__ gamma, const float* __restrict__ beta,
                         float* __restrict__ scale, float* __restrict__ shift, int N)
{
    const int c = blockIdx.x * 256 + threadIdx.x;
    if (c >= N) return;
    float s = 0.f, s2 = 0.f;
#pragma unroll
    for (int i = 0; i < 8; i++) { s += psum[i * N + c]; s2 += psum2[i * N + c]; }
    const float inv = 1.0f / (float)B_;
    const float mu  = s * inv;
    const float var = fmaxf(s2 * inv - mu * mu, 0.0f);
    const float sc  = __ldg(gamma + c) * rsqrtf(var + EPS_);
    scale[c] = sc;
    shift[c] = __ldg(beta + c) - (mu + __ldg(bias + c)) * sc;
}

// ---------------- BN apply + ReLU + tf32 round -----------------------------
__global__ void bn_apply_round(const float* __restrict__ hin, float* __restrict__ hout,
                               const float* __restrict__ scale,
                               const float* __restrict__ shift, int N)
{
    const int col = blockIdx.x * 256 + threadIdx.x;
    const size_t idx = (size_t)blockIdx.y * N + col;
    hout[idx] = to_tf32(fmaxf(fmaf(hin[idx], __ldg(scale + col), __ldg(shift + col)), 0.0f));
}

// ---------------- final: bn2(h2raw)@Wout + g@Wres + biases -> softmax ------
__global__ __launch_bounds__(256)
void final_kernel(const float* __restrict__ g, const float* __restrict__ h2raw,
                  const float* __restrict__ scale2, const float* __restrict__ shift2,
                  const float* __restrict__ Wout, const float* __restrict__ bout,
                  const float* __restrict__ Wres, const float* __restrict__ bres,
                  float* __restrict__ out)
{
    const int b = blockIdx.x;
    float acc[C_] = {};

    for (int k = threadIdx.x; k < H2_; k += 256) {
        const float hv = fmaxf(fmaf(h2raw[(size_t)b * H2_ + k],
                                    __ldg(scale2 + k), __ldg(shift2 + k)), 0.0f);
        const float* w = Wout + (size_t)k * C_;
#pragma unroll
        for (int c = 0; c < C_; c++) acc[c] = fmaf(hv, __ldg(w + c), acc[c]);
    }
    for (int j = threadIdx.x; j < G_; j += 256) {
        const float gv = g[(size_t)b * KP_ + j];
        const float* w = Wres + (size_t)j * C_;
#pragma unroll
        for (int c = 0; c < C_; c++) acc[c] = fmaf(gv, __ldg(w + c), acc[c]);
    }

#pragma unroll
    for (int c = 0; c < C_; c++)
#pragma unroll
        for (int off = 16; off > 0; off >>= 1)
            acc[c] += __shfl_down_sync(0xFFFFFFFFu, acc[c], off);

    __shared__ float red[8][C_];
    const int warp = threadIdx.x >> 5;
    const int lane = threadIdx.x & 31;
    if (lane == 0)
#pragma unroll
        for (int c = 0; c < C_; c++) red[warp][c] = acc[c];
    __syncthreads();

    if (threadIdx.x == 0) {
        float logits[C_];
#pragma unroll
        for (int c = 0; c < C_; c++) {
            float v = __ldg(bout + c) + __ldg(bres + c);
#pragma unroll
            for (int w = 0; w < 8; w++) v += red[w][c];
            logits[c] = v;
        }
        float m = logits[0];
#pragma unroll
        for (int c = 1; c < C_; c++) m = fmaxf(m, logits[c]);
        float sum = 0.f;
#pragma unroll
        for (int c = 0; c < C_; c++) { logits[c] = __expf(logits[c] - m); sum += logits[c]; }
        const float inv = 1.0f / sum;
#pragma unroll
        for (int c = 0; c < C_; c++) out[(size_t)b * C_ + c] = logits[c] * inv;
    }
}

// ---------------- launch ----------------------------------------------------
extern "C" void kernel_launch(void* const* d_in, const int* in_sizes, int n_in,
                              void* d_out, int out_size)
{
    const float* x      = (const float*)d_in[0];
    const float* gene_w = (const float*)d_in[1];
    const float* gene_b = (const float*)d_in[2];
    const float* W1     = (const float*)d_in[3];
    const float* b1     = (const float*)d_in[4];
    const float* gamma1 = (const float*)d_in[5];
    const float* beta1  = (const float*)d_in[6];
    const float* W2     = (const float*)d_in[7];
    const float* b2     = (const float*)d_in[8];
    const float* gamma2 = (const float*)d_in[9];
    const float* beta2  = (const float*)d_in[10];
    const float* Wout   = (const float*)d_in[11];
    const float* bout   = (const float*)d_in[12];
    const float* Wres   = (const float*)d_in[13];
    const float* bres   = (const float*)d_in[14];
    float* out = (float*)d_out;

    float *g_p, *w1_p, *w2_p, *h1_p, *h1a_p, *h2_p;
    float *sc1_p, *sh1_p, *sc2_p, *sh2_p, *ps_p, *ps2_p;
    cudaGetSymbolAddress((void**)&g_p,   d_g);
    cudaGetSymbolAddress((void**)&w1_p,  d_W1p);
    cudaGetSymbolAddress((void**)&w2_p,  d_W2r);
    cudaGetSymbolAddress((void**)&h1_p,  d_h1);
    cudaGetSymbolAddress((void**)&h1a_p, d_h1a);
    cudaGetSymbolAddress((void**)&h2_p,  d_h2);
    cudaGetSymbolAddress((void**)&sc1_p, d_scale1);
    cudaGetSymbolAddress((void**)&sh1_p, d_shift1);
    cudaGetSymbolAddress((void**)&sc2_p, d_scale2);
    cudaGetSymbolAddress((void**)&sh2_p, d_shift2);
    cudaGetSymbolAddress((void**)&ps_p,  d_psum);
    cudaGetSymbolAddress((void**)&ps2_p, d_psum2);

    // 0) weight prep (round + pad)
    prep_w1<<<(KP_ * H1_) / 256, 256>>>(W1, w1_p);
    prep_w2<<<(H1_ * H2_) / 256, 256>>>(W2, w2_p);

    // 1) grouped gene layer -> g (tf32, K-padded)
    gene_kernel<<<dim3((G_ + GPB - 1) / GPB, B_), GPB>>>(x, gene_w, gene_b, g_p);

    // 2) h1raw = g @ W1p  (wmma tf32, cp.async double-buffered, 4 CTAs/SM)
    wgemm<<<dim3(H1_ / WBN, B_ / WBM), 128>>>(g_p, w1_p, h1_p, B_, H1_, KP_);

    // 3) BN1 -> scale1/shift1 (b1 folded); apply+round -> h1a
    bn_part<<<dim3(H1_ / 64, 8), dim3(16, 32)>>>(h1_p, ps_p, ps2_p, H1_);
    bn_final<<<(H1_ + 255) / 256, 256>>>(ps_p, ps2_p, b1, gamma1, beta1, sc1_p, sh1_p, H1_);
    bn_apply_round<<<dim3(H1_ / 256, B_), 256>>>(h1_p, h1a_p, sc1_p, sh1_p, H1_);

    // 4) h2raw = h1a @ W2r
    wgemm<<<dim3(H2_ / WBN, B_ / WBM), 128>>>(h1a_p, w2_p, h2_p, B_, H2_, H1_);

    // 5) BN2 -> scale2/shift2
    bn_part<<<dim3(H2_ / 64, 8), dim3(16, 32)>>>(h2_p, ps_p, ps2_p, H2_);
    bn_final<<<(H2_ + 255) / 256, 256>>>(ps_p, ps2_p, b2, gamma2, beta2, sc2_p, sh2_p, H2_);

    // 6) fused output heads + softmax
    final_kernel<<<B_, 256>>>(g_p, h2_p, sc2_p, sh2_p, Wout, bout, Wres, bres, out);
}